// round 16
// baseline (speedup 1.0000x reference)
#include <cuda_runtime.h>
#include <cuda_fp16.h>
#include <cstdint>

#define E_ 8
#define D_ 512
#define F_ 2048
#define N_ 4096
#define KSPLIT 2

#define BK 32                      // k halves per stage (2 x k16 sub-blocks)
#define NSTG 3

#define A_STRIDE 40                // halves; 20-word rows, LDSM conflict-free
#define B_STRIDE 136               // halves; LDSM conflict-free

#define ASTG_B (128 * A_STRIDE * 2)     // 10240 B per A stage
#define BSTG_B (32 * B_STRIDE * 2)      // 8704 B per B stage
#define BBASE_B (NSTG * ASTG_B)         // 30720
#define SMEM_B (BBASE_B + NSTG * BSTG_B)  // 56832

#define WSZ ((size_t)E_ * D_ * F_)
#define XSZ ((size_t)N_ * D_)

#define GATE_BLOCKS 512
#define PREP_TOTAL 1184            // single wave: 512 gate + 672 convert

#define NTILE2 4
#define NFLAGS (E_ * (N_ / 128) * NTILE2)   // 1024

// fused kernel block ranges
#define CONV_BLKS 512
#define G1_BLKS   (16 * 32 * 8)    // 4096
#define G2_START  (CONV_BLKS + G1_BLKS)   // 4608
#define G2_BLKS   (8 * 32 * 8)     // 2048
#define FUSED_BLKS (G2_START + G2_BLKS)   // 6656

// g_sync layout
#define FLAG_OFF   9
#define HDONE_OFF  (9 + NFLAGS)            // 1033: h_done[E_*32]
#define W2DONE_OFF (HDONE_OFF + 256)       // 1289: w2_done[16]
#define SYNC_INTS  (W2DONE_OFF + 16)       // 1305

// ---------------- scratch (no allocations allowed) ----------------
// g_sync: [0..7] counts, [8] gate-done, [9..) tile flags, h_done, w2_done
__device__ int g_sync[SYNC_INTS];
__device__ int g_expert[N_];
__device__ int g_pos[N_];
__device__ int g_row2tok[N_];
__device__ __align__(16) __half g_W1h[WSZ];            // W1 natural [e][d][f], fp16
__device__ __align__(16) __half g_W2h[WSZ];            // W2 natural [e][f][d], fp16
__device__ __align__(16) __half g_xh[XSZ];             // x fp16
__device__ __align__(16) __half g_H[(size_t)N_ * F_];  // hidden fp16
__device__ __align__(16) float  g_part[(size_t)N_ * D_];  // single partial buffer

// ---------------- helpers ----------------
__device__ __forceinline__ int imin(int a, int b) { return a < b ? a : b; }

__device__ __forceinline__ void cp_async16_s(uint32_t sm, const void* gm) {
    asm volatile("cp.async.cg.shared.global [%0], [%1], 16;" :: "r"(sm), "l"(gm));
}
__device__ __forceinline__ void cp_commit() { asm volatile("cp.async.commit_group;"); }
__device__ __forceinline__ void cp_wait1()  { asm volatile("cp.async.wait_group 1;"); }

__device__ __forceinline__ void ldsm_x4(uint32_t r[4], uint32_t addr) {
    asm volatile("ldmatrix.sync.aligned.m8n8.x4.shared.b16 {%0,%1,%2,%3}, [%4];"
                 : "=r"(r[0]), "=r"(r[1]), "=r"(r[2]), "=r"(r[3]) : "r"(addr));
}
__device__ __forceinline__ void ldsm_x4_t(uint32_t r[4], uint32_t addr) {
    asm volatile("ldmatrix.sync.aligned.m8n8.x4.trans.shared.b16 {%0,%1,%2,%3}, [%4];"
                 : "=r"(r[0]), "=r"(r[1]), "=r"(r[2]), "=r"(r[3]) : "r"(addr));
}

__device__ __forceinline__ void mma_f16(float c[4], const uint32_t a[4],
                                        uint32_t b0, uint32_t b1) {
    asm volatile(
        "mma.sync.aligned.m16n8k16.row.col.f32.f16.f16.f32 "
        "{%0,%1,%2,%3}, {%4,%5,%6,%7}, {%8,%9}, {%0,%1,%2,%3};"
        : "+f"(c[0]), "+f"(c[1]), "+f"(c[2]), "+f"(c[3])
        : "r"(a[0]), "r"(a[1]), "r"(a[2]), "r"(a[3]), "r"(b0), "r"(b1));
}

__device__ __forceinline__ int expert_off(int e) {
    int s = 0;
#pragma unroll
    for (int i = 0; i < E_; i++) if (i < e) s += g_sync[i];
    return s;
}

__device__ __forceinline__ void cvt_chunk(const float4* src, __half* dst, size_t j) {
    float4 v = src[j];
    __half2 h0 = __floats2half2_rn(v.x, v.y);
    __half2 h1 = __floats2half2_rn(v.z, v.w);
    reinterpret_cast<uint2*>(dst)[j] = make_uint2(*(uint32_t*)&h0, *(uint32_t*)&h1);
}

// MLP-4 converter: batch 4 independent loads before converting/storing
__device__ __forceinline__ void cvt_range(const float4* src, __half* dst,
                                          size_t i0, size_t stride, size_t n) {
    size_t i = i0;
    for (; i + 3 * stride < n; i += 4 * stride) {
        float4 v0 = src[i];
        float4 v1 = src[i + stride];
        float4 v2 = src[i + 2 * stride];
        float4 v3 = src[i + 3 * stride];
        __half2 a0 = __floats2half2_rn(v0.x, v0.y), a1 = __floats2half2_rn(v0.z, v0.w);
        __half2 b0 = __floats2half2_rn(v1.x, v1.y), b1 = __floats2half2_rn(v1.z, v1.w);
        __half2 c0 = __floats2half2_rn(v2.x, v2.y), c1 = __floats2half2_rn(v2.z, v2.w);
        __half2 d0 = __floats2half2_rn(v3.x, v3.y), d1 = __floats2half2_rn(v3.z, v3.w);
        reinterpret_cast<uint2*>(dst)[i]              = make_uint2(*(uint32_t*)&a0, *(uint32_t*)&a1);
        reinterpret_cast<uint2*>(dst)[i + stride]     = make_uint2(*(uint32_t*)&b0, *(uint32_t*)&b1);
        reinterpret_cast<uint2*>(dst)[i + 2 * stride] = make_uint2(*(uint32_t*)&c0, *(uint32_t*)&c1);
        reinterpret_cast<uint2*>(dst)[i + 3 * stride] = make_uint2(*(uint32_t*)&d0, *(uint32_t*)&d1);
    }
    for (; i < n; i += stride) cvt_chunk(src, dst, i);
}

// ---------------- prep: W1->fp16 + gate (smem Wg) + x->fp16 + assign ----------
__global__ void prep_gate_kernel(const float* __restrict__ x,
                                 const float* __restrict__ Wg,
                                 const float* __restrict__ bg,
                                 const float* __restrict__ W1) {
    const int bid = blockIdx.x;
    if (bid >= GATE_BLOCKS) {
        cvt_range((const float4*)W1, g_W1h,
                  (size_t)(bid - GATE_BLOCKS) * blockDim.x + threadIdx.x,
                  (size_t)(PREP_TOTAL - GATE_BLOCKS) * blockDim.x, WSZ / 4);
        return;
    }
    // ---- gate: Wg staged in smem as [t][d4][e] ----
    __shared__ float sWg[4096];     // 16 KB
    {
        const float4* wg4 = reinterpret_cast<const float4*>(Wg);
#pragma unroll
        for (int k = 0; k < 4; k++) {
            int j = threadIdx.x + k * 256;
            float4 v = wg4[j];
            int d  = j >> 1;
            int e0 = (j & 1) * 4;
            int t  = d & 3, d4 = d >> 2;
            *reinterpret_cast<float4*>(&sWg[t * 1024 + d4 * 8 + e0]) = v;
        }
    }
    __syncthreads();

    int tok  = (bid * blockDim.x + threadIdx.x) >> 5;
    int lane = threadIdx.x & 31;
    {
        const float4* xr = reinterpret_cast<const float4*>(x) + (size_t)tok * (D_ / 4);
        uint2* xo = reinterpret_cast<uint2*>(g_xh) + (size_t)tok * (D_ / 4);

        float acc[E_];
#pragma unroll
        for (int e = 0; e < E_; e++) acc[e] = 0.f;

#pragma unroll
        for (int q = 0; q < 4; q++) {
            int d4 = lane + q * 32;
            float4 v = xr[d4];
            __half2 h0 = __floats2half2_rn(v.x, v.y);
            __half2 h1 = __floats2half2_rn(v.z, v.w);
            xo[d4] = make_uint2(*(uint32_t*)&h0, *(uint32_t*)&h1);
            float vv[4] = {v.x, v.y, v.z, v.w};
#pragma unroll
            for (int t = 0; t < 4; t++) {
                const float* wrow = &sWg[t * 1024 + d4 * 8];
                float4 w0 = *reinterpret_cast<const float4*>(wrow);
                float4 w1 = *reinterpret_cast<const float4*>(wrow + 4);
                acc[0] += vv[t] * w0.x; acc[1] += vv[t] * w0.y;
                acc[2] += vv[t] * w0.z; acc[3] += vv[t] * w0.w;
                acc[4] += vv[t] * w1.x; acc[5] += vv[t] * w1.y;
                acc[6] += vv[t] * w1.z; acc[7] += vv[t] * w1.w;
            }
        }
#pragma unroll
        for (int off = 16; off > 0; off >>= 1)
#pragma unroll
            for (int e = 0; e < E_; e++)
                acc[e] += __shfl_down_sync(0xFFFFFFFFu, acc[e], off);
        if (lane == 0) {
            float best = acc[0] + bg[0];
            int bi = 0;
#pragma unroll
            for (int e = 1; e < E_; e++) {
                float v = acc[e] + bg[e];
                if (v > best) { best = v; bi = e; }
            }
            int p = atomicAdd(&g_sync[bi], 1);
            g_expert[tok] = bi;
            g_pos[tok]    = p;
            __threadfence();
            atomicAdd(&g_sync[8], 1);
        }
    }

    // ---- blocks 0..15 (wave-1 resident): wait for all gates, assign rows ----
    if (bid < 16) {
        if (threadIdx.x == 0) {
            while (atomicAdd(&g_sync[8], 0) < N_) __nanosleep(64);
        }
        __syncthreads();
        __threadfence();
        int t = bid * 256 + threadIdx.x;
        int e = g_expert[t];
        int r = expert_off(e) + g_pos[t];
        g_row2tok[r] = t;
    }
}

// =====================================================================
// fp16 GEMM core, BK=32 (proven config): 256 thr, 8 warps (2x4),
// warp tile 64x32. 2 x k16 sub-blocks per iter, ONE __syncthreads per iter.
// 3-stage ring, wait_group 1. Dynamic smem SMEM_B bytes.
// =====================================================================
#define GEMM_CORE(NK, CWIDTH)                                                     \
    extern __shared__ __align__(16) char smem_raw[];                              \
    const int lane = tid & 31;                                                    \
    const int warp = tid >> 5;                                                    \
    const int wm   = warp >> 2;                                                   \
    const int wn   = warp & 3;                                                    \
    const uint32_t sA0 = (uint32_t)__cvta_generic_to_shared(smem_raw);            \
    const uint32_t sB0 = sA0 + BBASE_B;                                           \
    const uint32_t dstA0 = sA0 + (((tid >> 2) * A_STRIDE + (tid & 3) * 8)) * 2;   \
    const uint32_t dstA1 = dstA0 + 64 * A_STRIDE * 2;                             \
    const uint32_t dstB0 = sB0 + (((tid >> 4) * B_STRIDE + (tid & 15) * 8)) * 2;  \
    const uint32_t dstB1 = dstB0 + 16 * B_STRIDE * 2;                             \
    uint32_t adA[4], adB[2];                                                      \
    _Pragma("unroll")                                                             \
    for (int mt = 0; mt < 4; mt++)                                                \
        adA[mt] = sA0 + (((wm * 64 + mt * 16 + (lane & 15)) * A_STRIDE            \
                          + (lane >> 4) * 8)) * 2;                                \
    _Pragma("unroll")                                                             \
    for (int pr = 0; pr < 2; pr++) {                                              \
        const int j = lane >> 3;                                                  \
        const int kr = (j & 1) * 8 + (lane & 7);                                  \
        const int ncl = wn * 32 + pr * 16 + (j >> 1) * 8;                         \
        adB[pr] = sB0 + (kr * B_STRIDE + ncl) * 2;                                \
    }                                                                             \
    float acc[4][4][4];                                                           \
    _Pragma("unroll") for (int i = 0; i < 4; i++)                                 \
    _Pragma("unroll") for (int j = 0; j < 4; j++)                                 \
    _Pragma("unroll") for (int q = 0; q < 4; q++) acc[i][j][q] = 0.f;             \
    _Pragma("unroll")                                                             \
    for (int s = 0; s < 2; s++) {                                                 \
        cp_async16_s(dstA0 + s * ASTG_B, ap0 + (size_t)s * BK);                   \
        cp_async16_s(dstA1 + s * ASTG_B, ap1 + (size_t)s * BK);                   \
        cp_async16_s(dstB0 + s * BSTG_B, bp0 + (size_t)s * BK * (CWIDTH));        \
        cp_async16_s(dstB1 + s * BSTG_B, bp1 + (size_t)s * BK * (CWIDTH));        \
        cp_commit();                                                              \
    }                                                                             \
    for (int it = 0; it < (NK); ++it) {                                           \
        cp_wait1();                                                               \
        __syncthreads();                                                          \
        if (it + 2 < (NK)) {                                                      \
            const int s = (it + 2) % NSTG;                                        \
            cp_async16_s(dstA0 + s * ASTG_B, ap0 + (size_t)(it + 2) * BK);        \
            cp_async16_s(dstA1 + s * ASTG_B, ap1 + (size_t)(it + 2) * BK);        \
            cp_async16_s(dstB0 + s * BSTG_B, bp0 + (size_t)(it + 2) * BK * (CWIDTH)); \
            cp_async16_s(dstB1 + s * BSTG_B, bp1 + (size_t)(it + 2) * BK * (CWIDTH)); \
        }                                                                         \
        cp_commit();                                                              \
        const int cur = it % NSTG;                                                \
        const uint32_t oA = cur * ASTG_B;                                         \
        const uint32_t oB = cur * BSTG_B;                                         \
        _Pragma("unroll")                                                         \
        for (int sub = 0; sub < 2; ++sub) {                                       \
            const uint32_t sAoff = oA + sub * 32;                                 \
            const uint32_t sBoff = oB + sub * 16 * B_STRIDE * 2;                  \
            uint32_t a[4][4], bb[2][4];                                           \
            _Pragma("unroll")                                                     \
            for (int mt = 0; mt < 4; mt++) ldsm_x4(a[mt], adA[mt] + sAoff);       \
            _Pragma("unroll")                                                     \
            for (int pr = 0; pr < 2; pr++) ldsm_x4_t(bb[pr], adB[pr] + sBoff);    \
            _Pragma("unroll")                                                     \
            for (int mt = 0; mt < 4; mt++)                                        \
            _Pragma("unroll")                                                     \
            for (int nt = 0; nt < 4; nt++)                                        \
                mma_f16(acc[mt][nt], a[mt], bb[nt >> 1][(nt & 1) * 2],            \
                        bb[nt >> 1][(nt & 1) * 2 + 1]);                           \
        }                                                                         \
    }

// =====================================================================
// Fused: W2 convert (blocks [0,512)) -> gemm1 (blocks [512,4608)) ->
// gemm2 (blocks [4608,6656)), flag-gated dataflow. In-order dispatch
// guarantees every consumer spin waits on a placed (running) producer.
// =====================================================================
__global__ __launch_bounds__(256, 2)
void fused_gemms(const float* __restrict__ b1, const float* __restrict__ W2,
                 const float* __restrict__ b2, float* __restrict__ out) {
    const int bid = blockIdx.x;
    const int tid = threadIdx.x;

    if (bid < CONV_BLKS) {
        // ---- W2 fp32->fp16: region r=(e,kp) handled by 32 blocks ----
        const int r = bid >> 5, sub = bid & 31;
        const size_t base = (size_t)r * 131072 + (size_t)sub * 4096;  // float4 units
        const float4* src = (const float4*)W2;
#pragma unroll
        for (int k = 0; k < 4; k++) {
            size_t i = base + tid + (size_t)k * 1024;
            float4 v0 = src[i], v1 = src[i + 256], v2 = src[i + 512], v3 = src[i + 768];
            __half2 a0 = __floats2half2_rn(v0.x, v0.y), a1 = __floats2half2_rn(v0.z, v0.w);
            __half2 b0 = __floats2half2_rn(v1.x, v1.y), b1h = __floats2half2_rn(v1.z, v1.w);
            __half2 c0 = __floats2half2_rn(v2.x, v2.y), c1 = __floats2half2_rn(v2.z, v2.w);
            __half2 d0 = __floats2half2_rn(v3.x, v3.y), d1 = __floats2half2_rn(v3.z, v3.w);
            reinterpret_cast<uint2*>(g_W2h)[i]       = make_uint2(*(uint32_t*)&a0, *(uint32_t*)&a1);
            reinterpret_cast<uint2*>(g_W2h)[i + 256] = make_uint2(*(uint32_t*)&b0, *(uint32_t*)&b1h);
            reinterpret_cast<uint2*>(g_W2h)[i + 512] = make_uint2(*(uint32_t*)&c0, *(uint32_t*)&c1);
            reinterpret_cast<uint2*>(g_W2h)[i + 768] = make_uint2(*(uint32_t*)&d0, *(uint32_t*)&d1);
        }
        __threadfence();
        __syncthreads();
        if (tid == 0) atomicAdd(&g_sync[W2DONE_OFF + r], 1);
        return;
    }

    if (bid < G2_START) {
        // ---- GEMM1: H = fp16(relu(x @ W1 + b1)) ----
        const int g1 = bid - CONV_BLKS;
        const int bx = g1 & 15, by = (g1 >> 4) & 31, e = g1 >> 9;
        const int cnt = g_sync[e];
        const int m0  = by * 128;
        if (m0 >= cnt) return;
        const int off = expert_off(e);
        const int n0  = bx * 128;

        const int ar0 = imin(m0 + (tid >> 2), cnt - 1);
        const int ar1 = imin(m0 + (tid >> 2) + 64, cnt - 1);
        const __half* ap0 = g_xh + (size_t)g_row2tok[off + ar0] * D_ + (tid & 3) * 8;
        const __half* ap1 = g_xh + (size_t)g_row2tok[off + ar1] * D_ + (tid & 3) * 8;
        const __half* bp0 = g_W1h + (size_t)e * D_ * F_ + (size_t)(tid >> 4) * F_ + n0 + (tid & 15) * 8;
        const __half* bp1 = bp0 + (size_t)16 * F_;

        GEMM_CORE(D_ / BK, F_)     // 16 iters

        const float* b1e = b1 + (size_t)e * F_;
#pragma unroll
        for (int mt = 0; mt < 4; ++mt) {
            const int rb = m0 + wm * 64 + mt * 16 + (lane >> 2);
#pragma unroll
            for (int half = 0; half < 2; ++half) {
                const int r = rb + half * 8;
                if (r < cnt) {
                    __half* Hrow = g_H + (size_t)(off + r) * F_;
#pragma unroll
                    for (int nt = 0; nt < 4; ++nt) {
                        const int c = n0 + wn * 32 + nt * 8 + (lane & 3) * 2;
                        float v0 = fmaxf(acc[mt][nt][half * 2 + 0] + b1e[c],     0.f);
                        float v1 = fmaxf(acc[mt][nt][half * 2 + 1] + b1e[c + 1], 0.f);
                        __half2 h = __floats2half2_rn(v0, v1);
                        *reinterpret_cast<__half2*>(Hrow + c) = h;
                    }
                }
            }
        }
        __threadfence();
        __syncthreads();
        if (tid == 0) atomicAdd(&g_sync[HDONE_OFF + e * 32 + by], 1);
        return;
    }

    // ---- GEMM2 (split-K=2, single-partial fused reduce) ----
    {
        const int g2 = bid - G2_START;
        const int bx = g2 & 7, by = (g2 >> 3) & 31, e = g2 >> 8;
        const int cnt = g_sync[e];
        const int m0  = by * 128;
        if (m0 >= cnt) return;
        const int off = expert_off(e);
        const int kp  = bx >> 2;
        const int ni  = bx & 3;
        const int n0  = ni * 128;
        const int kbase = kp * (F_ / KSPLIT);
        int* flag = &g_sync[FLAG_OFF + (e * (N_ / 128) + by) * NTILE2 + ni];

        // wait for W2 region and H m-tile (producers are placed -> no deadlock)
        if (tid == 0) {
            while (atomicAdd(&g_sync[W2DONE_OFF + e * 2 + kp], 0) < 32) __nanosleep(64);
            while (atomicAdd(&g_sync[HDONE_OFF + e * 32 + by], 0) < 16) __nanosleep(64);
        }
        __syncthreads();
        __threadfence();

        const int ar0 = imin(m0 + (tid >> 2), cnt - 1);
        const int ar1 = imin(m0 + (tid >> 2) + 64, cnt - 1);
        const __half* ap0 = g_H + (size_t)(off + ar0) * F_ + kbase + (tid & 3) * 8;
        const __half* ap1 = g_H + (size_t)(off + ar1) * F_ + kbase + (tid & 3) * 8;
        const __half* bp0 = g_W2h + (size_t)e * D_ * F_ + (size_t)(kbase + (tid >> 4)) * D_ + n0 + (tid & 15) * 8;
        const __half* bp1 = bp0 + (size_t)16 * D_;

        GEMM_CORE((F_ / KSPLIT) / BK, D_)    // 32 iters

        __shared__ int s_old;
        if (tid == 0) s_old = atomicAdd(flag, 1);
        __syncthreads();

        if (s_old == 0) {
#pragma unroll
            for (int mt = 0; mt < 4; ++mt) {
                const int rb = m0 + wm * 64 + mt * 16 + (lane >> 2);
#pragma unroll
                for (int half = 0; half < 2; ++half) {
                    const int r = rb + half * 8;
                    if (r < cnt) {
                        float* prow = g_part + (size_t)(off + r) * D_;
#pragma unroll
                        for (int nt = 0; nt < 4; ++nt) {
                            const int c = n0 + wn * 32 + nt * 8 + (lane & 3) * 2;
                            float2 o;
                            o.x = acc[mt][nt][half * 2 + 0];
                            o.y = acc[mt][nt][half * 2 + 1];
                            *reinterpret_cast<float2*>(prow + c) = o;
                        }
                    }
                }
            }
            __threadfence();
            __syncthreads();
            if (tid == 0) atomicAdd(flag, 1);   // -> 2: data visible
            return;
        }

        if (tid == 0) {
            while (atomicAdd(flag, 0) < 2) __nanosleep(32);
        }
        __syncthreads();
        __threadfence();

        const float* b2e = b2 + (size_t)e * D_;
#pragma unroll
        for (int mt = 0; mt < 4; ++mt) {
            const int rb = m0 + wm * 64 + mt * 16 + (lane >> 2);
#pragma unroll
            for (int half = 0; half < 2; ++half) {
                const int r = rb + half * 8;
                if (r < cnt) {
                    const int tok = g_row2tok[off + r];
                    const float* prow = g_part + (size_t)(off + r) * D_;
                    float* dst = out + (size_t)tok * D_;
#pragma unroll
                    for (int nt = 0; nt < 4; ++nt) {
                        const int c = n0 + wn * 32 + nt * 8 + (lane & 3) * 2;
                        float2 p = *reinterpret_cast<const float2*>(prow + c);
                        float2 o;
                        o.x = (p.x + acc[mt][nt][half * 2 + 0]) + b2e[c];
                        o.y = (p.y + acc[mt][nt][half * 2 + 1]) + b2e[c + 1];
                        *reinterpret_cast<float2*>(dst + c) = o;
                    }
                }
            }
        }
    }
}

// ---------------- launch ----------------
extern "C" void kernel_launch(void* const* d_in, const int* in_sizes, int n_in,
                              void* d_out, int out_size) {
    const float* x  = (const float*)d_in[0];
    const float* Wg = (const float*)d_in[1];
    const float* bg = (const float*)d_in[2];
    const float* W1 = (const float*)d_in[3];
    const float* b1 = (const float*)d_in[4];
    const float* W2 = (const float*)d_in[5];
    const float* b2 = (const float*)d_in[6];
    float* out = (float*)d_out;

    cudaFuncSetAttribute(fused_gemms, cudaFuncAttributeMaxDynamicSharedMemorySize, SMEM_B);

    void* sync_addr = nullptr;
    cudaGetSymbolAddress(&sync_addr, g_sync);
    cudaMemsetAsync(sync_addr, 0, SYNC_INTS * sizeof(int));

    prep_gate_kernel<<<PREP_TOTAL, 256>>>(x, Wg, bg, W1);
    fused_gemms<<<FUSED_BLKS, 256, SMEM_B>>>(b1, W2, b2, out);
}

// round 17
// speedup vs baseline: 1.0510x; 1.0510x over previous
#include <cuda_runtime.h>
#include <cuda_fp16.h>
#include <cstdint>

#define E_ 8
#define D_ 512
#define F_ 2048
#define N_ 4096
#define KSPLIT 2

#define BK 32                      // k halves per stage (2 x k16 sub-blocks)
#define NSTG 3

#define A_STRIDE 40                // halves; 20-word rows, LDSM conflict-free
#define B_STRIDE 136               // halves; LDSM conflict-free

#define ASTG_B (128 * A_STRIDE * 2)     // 10240 B per A stage
#define BSTG_B (32 * B_STRIDE * 2)      // 8704 B per B stage
#define BBASE_B (NSTG * ASTG_B)         // 30720
#define SMEM_B (BBASE_B + NSTG * BSTG_B)  // 56832

#define WSZ ((size_t)E_ * D_ * F_)
#define XSZ ((size_t)N_ * D_)

#define GATE_BLOCKS 512
#define PREP_TOTAL 1184            // single wave: 512 gate + 672 convert

#define NTILE2 4
#define NFLAGS (E_ * (N_ / 128) * NTILE2)   // 1024

// fused kernel block ranges: gemm1 FIRST, W2 conv (fills gemm1 slack), gemm2 LAST
#define G1_BLKS    (16 * 32 * 8)            // 4096
#define CONV_START G1_BLKS                  // 4096
#define CONV_BLKS  512
#define G2_START   (CONV_START + CONV_BLKS) // 4608
#define G2_BLKS    (8 * 32 * 8)             // 2048
#define FUSED_BLKS (G2_START + G2_BLKS)     // 6656

// g_sync layout
#define FLAG_OFF   9
#define HDONE_OFF  (9 + NFLAGS)            // h_done[E_*32]
#define W2DONE_OFF (HDONE_OFF + 256)       // w2_done[16]
#define SYNC_INTS  (W2DONE_OFF + 16)

// ---------------- scratch (no allocations allowed) ----------------
__device__ int g_sync[SYNC_INTS];
__device__ int g_expert[N_];
__device__ int g_pos[N_];
__device__ int g_row2tok[N_];
__device__ __align__(16) __half g_W1h[WSZ];            // W1 natural [e][d][f], fp16
__device__ __align__(16) __half g_W2h[WSZ];            // W2 natural [e][f][d], fp16
__device__ __align__(16) __half g_xh[XSZ];             // x fp16
__device__ __align__(16) __half g_H[(size_t)N_ * F_];  // hidden fp16
__device__ __align__(16) float  g_part[(size_t)N_ * D_];  // single partial buffer

// ---------------- helpers ----------------
__device__ __forceinline__ int imin(int a, int b) { return a < b ? a : b; }

__device__ __forceinline__ void cp_async16_s(uint32_t sm, const void* gm) {
    asm volatile("cp.async.cg.shared.global [%0], [%1], 16;" :: "r"(sm), "l"(gm));
}
__device__ __forceinline__ void cp_commit() { asm volatile("cp.async.commit_group;"); }
__device__ __forceinline__ void cp_wait1()  { asm volatile("cp.async.wait_group 1;"); }

__device__ __forceinline__ void ldsm_x4(uint32_t r[4], uint32_t addr) {
    asm volatile("ldmatrix.sync.aligned.m8n8.x4.shared.b16 {%0,%1,%2,%3}, [%4];"
                 : "=r"(r[0]), "=r"(r[1]), "=r"(r[2]), "=r"(r[3]) : "r"(addr));
}
__device__ __forceinline__ void ldsm_x4_t(uint32_t r[4], uint32_t addr) {
    asm volatile("ldmatrix.sync.aligned.m8n8.x4.trans.shared.b16 {%0,%1,%2,%3}, [%4];"
                 : "=r"(r[0]), "=r"(r[1]), "=r"(r[2]), "=r"(r[3]) : "r"(addr));
}

__device__ __forceinline__ void mma_f16(float c[4], const uint32_t a[4],
                                        uint32_t b0, uint32_t b1) {
    asm volatile(
        "mma.sync.aligned.m16n8k16.row.col.f32.f16.f16.f32 "
        "{%0,%1,%2,%3}, {%4,%5,%6,%7}, {%8,%9}, {%0,%1,%2,%3};"
        : "+f"(c[0]), "+f"(c[1]), "+f"(c[2]), "+f"(c[3])
        : "r"(a[0]), "r"(a[1]), "r"(a[2]), "r"(a[3]), "r"(b0), "r"(b1));
}

__device__ __forceinline__ int expert_off(int e) {
    int s = 0;
#pragma unroll
    for (int i = 0; i < E_; i++) if (i < e) s += g_sync[i];
    return s;
}

__device__ __forceinline__ void cvt_chunk(const float4* src, __half* dst, size_t j) {
    float4 v = src[j];
    __half2 h0 = __floats2half2_rn(v.x, v.y);
    __half2 h1 = __floats2half2_rn(v.z, v.w);
    reinterpret_cast<uint2*>(dst)[j] = make_uint2(*(uint32_t*)&h0, *(uint32_t*)&h1);
}

// MLP-4 converter: batch 4 independent loads before converting/storing
__device__ __forceinline__ void cvt_range(const float4* src, __half* dst,
                                          size_t i0, size_t stride, size_t n) {
    size_t i = i0;
    for (; i + 3 * stride < n; i += 4 * stride) {
        float4 v0 = src[i];
        float4 v1 = src[i + stride];
        float4 v2 = src[i + 2 * stride];
        float4 v3 = src[i + 3 * stride];
        __half2 a0 = __floats2half2_rn(v0.x, v0.y), a1 = __floats2half2_rn(v0.z, v0.w);
        __half2 b0 = __floats2half2_rn(v1.x, v1.y), b1 = __floats2half2_rn(v1.z, v1.w);
        __half2 c0 = __floats2half2_rn(v2.x, v2.y), c1 = __floats2half2_rn(v2.z, v2.w);
        __half2 d0 = __floats2half2_rn(v3.x, v3.y), d1 = __floats2half2_rn(v3.z, v3.w);
        reinterpret_cast<uint2*>(dst)[i]              = make_uint2(*(uint32_t*)&a0, *(uint32_t*)&a1);
        reinterpret_cast<uint2*>(dst)[i + stride]     = make_uint2(*(uint32_t*)&b0, *(uint32_t*)&b1);
        reinterpret_cast<uint2*>(dst)[i + 2 * stride] = make_uint2(*(uint32_t*)&c0, *(uint32_t*)&c1);
        reinterpret_cast<uint2*>(dst)[i + 3 * stride] = make_uint2(*(uint32_t*)&d0, *(uint32_t*)&d1);
    }
    for (; i < n; i += stride) cvt_chunk(src, dst, i);
}

// ---------------- prep: W1->fp16 + gate (smem Wg) + x->fp16 + assign ----------
__global__ void prep_gate_kernel(const float* __restrict__ x,
                                 const float* __restrict__ Wg,
                                 const float* __restrict__ bg,
                                 const float* __restrict__ W1) {
    const int bid = blockIdx.x;
    if (bid >= GATE_BLOCKS) {
        cvt_range((const float4*)W1, g_W1h,
                  (size_t)(bid - GATE_BLOCKS) * blockDim.x + threadIdx.x,
                  (size_t)(PREP_TOTAL - GATE_BLOCKS) * blockDim.x, WSZ / 4);
        return;
    }
    // ---- gate: Wg staged in smem as [t][d4][e] ----
    __shared__ float sWg[4096];     // 16 KB
    {
        const float4* wg4 = reinterpret_cast<const float4*>(Wg);
#pragma unroll
        for (int k = 0; k < 4; k++) {
            int j = threadIdx.x + k * 256;
            float4 v = wg4[j];
            int d  = j >> 1;
            int e0 = (j & 1) * 4;
            int t  = d & 3, d4 = d >> 2;
            *reinterpret_cast<float4*>(&sWg[t * 1024 + d4 * 8 + e0]) = v;
        }
    }
    __syncthreads();

    int tok  = (bid * blockDim.x + threadIdx.x) >> 5;
    int lane = threadIdx.x & 31;
    {
        const float4* xr = reinterpret_cast<const float4*>(x) + (size_t)tok * (D_ / 4);
        uint2* xo = reinterpret_cast<uint2*>(g_xh) + (size_t)tok * (D_ / 4);

        float acc[E_];
#pragma unroll
        for (int e = 0; e < E_; e++) acc[e] = 0.f;

#pragma unroll
        for (int q = 0; q < 4; q++) {
            int d4 = lane + q * 32;
            float4 v = xr[d4];
            __half2 h0 = __floats2half2_rn(v.x, v.y);
            __half2 h1 = __floats2half2_rn(v.z, v.w);
            xo[d4] = make_uint2(*(uint32_t*)&h0, *(uint32_t*)&h1);
            float vv[4] = {v.x, v.y, v.z, v.w};
#pragma unroll
            for (int t = 0; t < 4; t++) {
                const float* wrow = &sWg[t * 1024 + d4 * 8];
                float4 w0 = *reinterpret_cast<const float4*>(wrow);
                float4 w1 = *reinterpret_cast<const float4*>(wrow + 4);
                acc[0] += vv[t] * w0.x; acc[1] += vv[t] * w0.y;
                acc[2] += vv[t] * w0.z; acc[3] += vv[t] * w0.w;
                acc[4] += vv[t] * w1.x; acc[5] += vv[t] * w1.y;
                acc[6] += vv[t] * w1.z; acc[7] += vv[t] * w1.w;
            }
        }
#pragma unroll
        for (int off = 16; off > 0; off >>= 1)
#pragma unroll
            for (int e = 0; e < E_; e++)
                acc[e] += __shfl_down_sync(0xFFFFFFFFu, acc[e], off);
        if (lane == 0) {
            float best = acc[0] + bg[0];
            int bi = 0;
#pragma unroll
            for (int e = 1; e < E_; e++) {
                float v = acc[e] + bg[e];
                if (v > best) { best = v; bi = e; }
            }
            int p = atomicAdd(&g_sync[bi], 1);
            g_expert[tok] = bi;
            g_pos[tok]    = p;
            __threadfence();
            atomicAdd(&g_sync[8], 1);
        }
    }

    // ---- blocks 0..15 (wave-1 resident): wait for all gates, assign rows ----
    if (bid < 16) {
        if (threadIdx.x == 0) {
            while (atomicAdd(&g_sync[8], 0) < N_) __nanosleep(64);
        }
        __syncthreads();
        __threadfence();
        int t = bid * 256 + threadIdx.x;
        int e = g_expert[t];
        int r = expert_off(e) + g_pos[t];
        g_row2tok[r] = t;
    }
}

// =====================================================================
// fp16 GEMM core, BK=32 (proven config): 256 thr, 8 warps (2x4),
// warp tile 64x32. 2 x k16 sub-blocks per iter, ONE __syncthreads per iter.
// 3-stage ring, wait_group 1. Dynamic smem SMEM_B bytes.
// =====================================================================
#define GEMM_CORE(NK, CWIDTH)                                                     \
    extern __shared__ __align__(16) char smem_raw[];                              \
    const int lane = tid & 31;                                                    \
    const int warp = tid >> 5;                                                    \
    const int wm   = warp >> 2;                                                   \
    const int wn   = warp & 3;                                                    \
    const uint32_t sA0 = (uint32_t)__cvta_generic_to_shared(smem_raw);            \
    const uint32_t sB0 = sA0 + BBASE_B;                                           \
    const uint32_t dstA0 = sA0 + (((tid >> 2) * A_STRIDE + (tid & 3) * 8)) * 2;   \
    const uint32_t dstA1 = dstA0 + 64 * A_STRIDE * 2;                             \
    const uint32_t dstB0 = sB0 + (((tid >> 4) * B_STRIDE + (tid & 15) * 8)) * 2;  \
    const uint32_t dstB1 = dstB0 + 16 * B_STRIDE * 2;                             \
    uint32_t adA[4], adB[2];                                                      \
    _Pragma("unroll")                                                             \
    for (int mt = 0; mt < 4; mt++)                                                \
        adA[mt] = sA0 + (((wm * 64 + mt * 16 + (lane & 15)) * A_STRIDE            \
                          + (lane >> 4) * 8)) * 2;                                \
    _Pragma("unroll")                                                             \
    for (int pr = 0; pr < 2; pr++) {                                              \
        const int j = lane >> 3;                                                  \
        const int kr = (j & 1) * 8 + (lane & 7);                                  \
        const int ncl = wn * 32 + pr * 16 + (j >> 1) * 8;                         \
        adB[pr] = sB0 + (kr * B_STRIDE + ncl) * 2;                                \
    }                                                                             \
    float acc[4][4][4];                                                           \
    _Pragma("unroll") for (int i = 0; i < 4; i++)                                 \
    _Pragma("unroll") for (int j = 0; j < 4; j++)                                 \
    _Pragma("unroll") for (int q = 0; q < 4; q++) acc[i][j][q] = 0.f;             \
    _Pragma("unroll")                                                             \
    for (int s = 0; s < 2; s++) {                                                 \
        cp_async16_s(dstA0 + s * ASTG_B, ap0 + (size_t)s * BK);                   \
        cp_async16_s(dstA1 + s * ASTG_B, ap1 + (size_t)s * BK);                   \
        cp_async16_s(dstB0 + s * BSTG_B, bp0 + (size_t)s * BK * (CWIDTH));        \
        cp_async16_s(dstB1 + s * BSTG_B, bp1 + (size_t)s * BK * (CWIDTH));        \
        cp_commit();                                                              \
    }                                                                             \
    for (int it = 0; it < (NK); ++it) {                                           \
        cp_wait1();                                                               \
        __syncthreads();                                                          \
        if (it + 2 < (NK)) {                                                      \
            const int s = (it + 2) % NSTG;                                        \
            cp_async16_s(dstA0 + s * ASTG_B, ap0 + (size_t)(it + 2) * BK);        \
            cp_async16_s(dstA1 + s * ASTG_B, ap1 + (size_t)(it + 2) * BK);        \
            cp_async16_s(dstB0 + s * BSTG_B, bp0 + (size_t)(it + 2) * BK * (CWIDTH)); \
            cp_async16_s(dstB1 + s * BSTG_B, bp1 + (size_t)(it + 2) * BK * (CWIDTH)); \
        }                                                                         \
        cp_commit();                                                              \
        const int cur = it % NSTG;                                                \
        const uint32_t oA = cur * ASTG_B;                                         \
        const uint32_t oB = cur * BSTG_B;                                         \
        _Pragma("unroll")                                                         \
        for (int sub = 0; sub < 2; ++sub) {                                       \
            const uint32_t sAoff = oA + sub * 32;                                 \
            const uint32_t sBoff = oB + sub * 16 * B_STRIDE * 2;                  \
            uint32_t a[4][4], bb[2][4];                                           \
            _Pragma("unroll")                                                     \
            for (int mt = 0; mt < 4; mt++) ldsm_x4(a[mt], adA[mt] + sAoff);       \
            _Pragma("unroll")                                                     \
            for (int pr = 0; pr < 2; pr++) ldsm_x4_t(bb[pr], adB[pr] + sBoff);    \
            _Pragma("unroll")                                                     \
            for (int mt = 0; mt < 4; mt++)                                        \
            _Pragma("unroll")                                                     \
            for (int nt = 0; nt < 4; nt++)                                        \
                mma_f16(acc[mt][nt], a[mt], bb[nt >> 1][(nt & 1) * 2],            \
                        bb[nt >> 1][(nt & 1) * 2 + 1]);                           \
        }                                                                         \
    }

// =====================================================================
// Fused: gemm1 (blocks [0,4096)) -> W2 convert (blocks [4096,4608), fills
// gemm1's early-exit slack) -> gemm2 (blocks [4608,6656), flag-gated).
// In-order dispatch: every consumer spin waits on a placed producer.
// =====================================================================
__global__ __launch_bounds__(256, 2)
void fused_gemms(const float* __restrict__ b1, const float* __restrict__ W2,
                 const float* __restrict__ b2, float* __restrict__ out) {
    const int bid = blockIdx.x;
    const int tid = threadIdx.x;

    if (bid < G1_BLKS) {
        // ---- GEMM1: H = fp16(relu(x @ W1 + b1)) ----
        const int bx = bid & 15, by = (bid >> 4) & 31, e = bid >> 9;
        const int cnt = g_sync[e];
        const int m0  = by * 128;
        if (m0 >= cnt) return;
        const int off = expert_off(e);
        const int n0  = bx * 128;

        const int ar0 = imin(m0 + (tid >> 2), cnt - 1);
        const int ar1 = imin(m0 + (tid >> 2) + 64, cnt - 1);
        const __half* ap0 = g_xh + (size_t)g_row2tok[off + ar0] * D_ + (tid & 3) * 8;
        const __half* ap1 = g_xh + (size_t)g_row2tok[off + ar1] * D_ + (tid & 3) * 8;
        const __half* bp0 = g_W1h + (size_t)e * D_ * F_ + (size_t)(tid >> 4) * F_ + n0 + (tid & 15) * 8;
        const __half* bp1 = bp0 + (size_t)16 * F_;

        GEMM_CORE(D_ / BK, F_)     // 16 iters

        const float* b1e = b1 + (size_t)e * F_;
#pragma unroll
        for (int mt = 0; mt < 4; ++mt) {
            const int rb = m0 + wm * 64 + mt * 16 + (lane >> 2);
#pragma unroll
            for (int half = 0; half < 2; ++half) {
                const int r = rb + half * 8;
                if (r < cnt) {
                    __half* Hrow = g_H + (size_t)(off + r) * F_;
#pragma unroll
                    for (int nt = 0; nt < 4; ++nt) {
                        const int c = n0 + wn * 32 + nt * 8 + (lane & 3) * 2;
                        float v0 = fmaxf(acc[mt][nt][half * 2 + 0] + b1e[c],     0.f);
                        float v1 = fmaxf(acc[mt][nt][half * 2 + 1] + b1e[c + 1], 0.f);
                        __half2 h = __floats2half2_rn(v0, v1);
                        *reinterpret_cast<__half2*>(Hrow + c) = h;
                    }
                }
            }
        }
        __threadfence();
        __syncthreads();
        if (tid == 0) atomicAdd(&g_sync[HDONE_OFF + e * 32 + by], 1);
        return;
    }

    if (bid < G2_START) {
        // ---- W2 fp32->fp16: region r=(e,kp) handled by 32 blocks ----
        const int cb = bid - CONV_START;
        const int r = cb >> 5, sub = cb & 31;
        const size_t base = (size_t)r * 131072 + (size_t)sub * 4096;  // float4 units
        const float4* src = (const float4*)W2;
#pragma unroll
        for (int k = 0; k < 4; k++) {
            size_t i = base + tid + (size_t)k * 1024;
            float4 v0 = src[i], v1 = src[i + 256], v2 = src[i + 512], v3 = src[i + 768];
            __half2 a0 = __floats2half2_rn(v0.x, v0.y), a1 = __floats2half2_rn(v0.z, v0.w);
            __half2 b0 = __floats2half2_rn(v1.x, v1.y), b1h = __floats2half2_rn(v1.z, v1.w);
            __half2 c0 = __floats2half2_rn(v2.x, v2.y), c1 = __floats2half2_rn(v2.z, v2.w);
            __half2 d0 = __floats2half2_rn(v3.x, v3.y), d1 = __floats2half2_rn(v3.z, v3.w);
            reinterpret_cast<uint2*>(g_W2h)[i]       = make_uint2(*(uint32_t*)&a0, *(uint32_t*)&a1);
            reinterpret_cast<uint2*>(g_W2h)[i + 256] = make_uint2(*(uint32_t*)&b0, *(uint32_t*)&b1h);
            reinterpret_cast<uint2*>(g_W2h)[i + 512] = make_uint2(*(uint32_t*)&c0, *(uint32_t*)&c1);
            reinterpret_cast<uint2*>(g_W2h)[i + 768] = make_uint2(*(uint32_t*)&d0, *(uint32_t*)&d1);
        }
        __threadfence();
        __syncthreads();
        if (tid == 0) atomicAdd(&g_sync[W2DONE_OFF + r], 1);
        return;
    }

    // ---- GEMM2 (split-K=2, single-partial fused reduce) ----
    {
        const int g2 = bid - G2_START;
        const int bx = g2 & 7, by = (g2 >> 3) & 31, e = g2 >> 8;
        const int cnt = g_sync[e];
        const int m0  = by * 128;
        if (m0 >= cnt) return;
        const int off = expert_off(e);
        const int kp  = bx >> 2;
        const int ni  = bx & 3;
        const int n0  = ni * 128;
        const int kbase = kp * (F_ / KSPLIT);
        int* flag = &g_sync[FLAG_OFF + (e * (N_ / 128) + by) * NTILE2 + ni];

        // wait for W2 region and H m-tile (producers dispatched earlier)
        if (tid == 0) {
            while (atomicAdd(&g_sync[W2DONE_OFF + e * 2 + kp], 0) < 32) __nanosleep(64);
            while (atomicAdd(&g_sync[HDONE_OFF + e * 32 + by], 0) < 16) __nanosleep(64);
        }
        __syncthreads();
        __threadfence();

        const int ar0 = imin(m0 + (tid >> 2), cnt - 1);
        const int ar1 = imin(m0 + (tid >> 2) + 64, cnt - 1);
        const __half* ap0 = g_H + (size_t)(off + ar0) * F_ + kbase + (tid & 3) * 8;
        const __half* ap1 = g_H + (size_t)(off + ar1) * F_ + kbase + (tid & 3) * 8;
        const __half* bp0 = g_W2h + (size_t)e * D_ * F_ + (size_t)(kbase + (tid >> 4)) * D_ + n0 + (tid & 15) * 8;
        const __half* bp1 = bp0 + (size_t)16 * D_;

        GEMM_CORE((F_ / KSPLIT) / BK, D_)    // 32 iters

        __shared__ int s_old;
        if (tid == 0) s_old = atomicAdd(flag, 1);
        __syncthreads();

        if (s_old == 0) {
#pragma unroll
            for (int mt = 0; mt < 4; ++mt) {
                const int rb = m0 + wm * 64 + mt * 16 + (lane >> 2);
#pragma unroll
                for (int half = 0; half < 2; ++half) {
                    const int r = rb + half * 8;
                    if (r < cnt) {
                        float* prow = g_part + (size_t)(off + r) * D_;
#pragma unroll
                        for (int nt = 0; nt < 4; ++nt) {
                            const int c = n0 + wn * 32 + nt * 8 + (lane & 3) * 2;
                            float2 o;
                            o.x = acc[mt][nt][half * 2 + 0];
                            o.y = acc[mt][nt][half * 2 + 1];
                            *reinterpret_cast<float2*>(prow + c) = o;
                        }
                    }
                }
            }
            __threadfence();
            __syncthreads();
            if (tid == 0) atomicAdd(flag, 1);   // -> 2: data visible
            return;
        }

        if (tid == 0) {
            while (atomicAdd(flag, 0) < 2) __nanosleep(32);
        }
        __syncthreads();
        __threadfence();

        const float* b2e = b2 + (size_t)e * D_;
#pragma unroll
        for (int mt = 0; mt < 4; ++mt) {
            const int rb = m0 + wm * 64 + mt * 16 + (lane >> 2);
#pragma unroll
            for (int half = 0; half < 2; ++half) {
                const int r = rb + half * 8;
                if (r < cnt) {
                    const int tok = g_row2tok[off + r];
                    const float* prow = g_part + (size_t)(off + r) * D_;
                    float* dst = out + (size_t)tok * D_;
#pragma unroll
                    for (int nt = 0; nt < 4; ++nt) {
                        const int c = n0 + wn * 32 + nt * 8 + (lane & 3) * 2;
                        float2 p = *reinterpret_cast<const float2*>(prow + c);
                        float2 o;
                        o.x = (p.x + acc[mt][nt][half * 2 + 0]) + b2e[c];
                        o.y = (p.y + acc[mt][nt][half * 2 + 1]) + b2e[c + 1];
                        *reinterpret_cast<float2*>(dst + c) = o;
                    }
                }
            }
        }
    }
}

// ---------------- launch ----------------
extern "C" void kernel_launch(void* const* d_in, const int* in_sizes, int n_in,
                              void* d_out, int out_size) {
    const float* x  = (const float*)d_in[0];
    const float* Wg = (const float*)d_in[1];
    const float* bg = (const float*)d_in[2];
    const float* W1 = (const float*)d_in[3];
    const float* b1 = (const float*)d_in[4];
    const float* W2 = (const float*)d_in[5];
    const float* b2 = (const float*)d_in[6];
    float* out = (float*)d_out;

    cudaFuncSetAttribute(fused_gemms, cudaFuncAttributeMaxDynamicSharedMemorySize, SMEM_B);

    void* sync_addr = nullptr;
    cudaGetSymbolAddress(&sync_addr, g_sync);
    cudaMemsetAsync(sync_addr, 0, SYNC_INTS * sizeof(int));

    prep_gate_kernel<<<PREP_TOTAL, 256>>>(x, Wg, bg, W1);
    fused_gemms<<<FUSED_BLKS, 256, SMEM_B>>>(b1, W2, b2, out);
}